// round 1
// baseline (speedup 1.0000x reference)
#include <cuda_runtime.h>

#define NN 50000
#define EE 400000
#define HH 128
#define NREL 20
#define CH 512

// Scratch (device globals; no allocation allowed)
__device__ float g_deg[2 * NREL * NN];   // [r][0]=out-deg(src), [r][1]=in-deg(dst)
__device__ float g_u[NREL * NN];         // u_r = M_r^T 1
__device__ float g_sigma[NREL];          // sum of u_r
__device__ float g_w[16 * NN];           // 16 w vectors per src-ntype group (reused)
__device__ float g_y[80 * 768];          // y[(r'*4 + r%4)][c] = w^T x
__device__ float g_t[NREL * HH];         // t_r = u_r^T h1_{s(r)}

// RELS dst ntype ids (stock=0, financial=1, macro=2, news=3, policy=4)
__constant__ int c_dst[NREL] = {1,2,3,4, 2,0,3,4, 0,1,3,4, 0,1,2,4, 0,2,3,1};
// relations whose dst == given ntype
__constant__ int c_inrel[5][4] = {{5,8,12,16},{0,9,13,19},{1,4,14,17},{2,6,10,18},{3,7,11,15}};
__constant__ int c_F[5] = {5,16,21,768,768};

__global__ void k_zero_pre() {
    const int T1 = 2 * NREL * NN, T2 = NREL * NN, T3 = 80 * 768;
    for (int i = blockIdx.x * blockDim.x + threadIdx.x; i < T1 + T2 + T3;
         i += gridDim.x * blockDim.x) {
        if (i < T1) g_deg[i] = 0.f;
        else if (i < T1 + T2) g_u[i - T1] = 0.f;
        else g_y[i - T1 - T2] = 0.f;
    }
}

__global__ void k_zero_w() {
    for (int i = blockIdx.x * blockDim.x + threadIdx.x; i < 16 * NN;
         i += gridDim.x * blockDim.x) g_w[i] = 0.f;
}

__global__ void k_degree(const int* __restrict__ edges) {
    int e = blockIdx.x * blockDim.x + threadIdx.x;
    if (e >= EE) return;
    int r = blockIdx.y;
    const int* base = edges + r * 2 * EE;
    atomicAdd(&g_deg[(2 * r) * NN + base[e]], 1.f);
    atomicAdd(&g_deg[(2 * r + 1) * NN + base[EE + e]], 1.f);
}

__global__ void k_u(const int* __restrict__ edges) {
    int e = blockIdx.x * blockDim.x + threadIdx.x;
    if (e >= EE) return;
    int r = blockIdx.y;
    const int* base = edges + r * 2 * EE;
    int s = base[e], d = base[EE + e];
    float ns = rsqrtf(fmaxf(g_deg[(2 * r) * NN + s], 1.f));
    float nd = rsqrtf(fmaxf(g_deg[(2 * r + 1) * NN + d], 1.f));
    atomicAdd(&g_u[r * NN + s], ns * nd);
}

__global__ void k_sigma() {
    int r = blockIdx.x;
    float a = 0.f;
    for (int i = threadIdx.x; i < NN; i += blockDim.x) a += g_u[r * NN + i];
    __shared__ float sred[256];
    sred[threadIdx.x] = a;
    __syncthreads();
    for (int st = 128; st > 0; st >>= 1) {
        if (threadIdx.x < st) sred[threadIdx.x] += sred[threadIdx.x + st];
        __syncthreads();
    }
    if (threadIdx.x == 0) g_sigma[r] = sred[0];
}

// For src-ntype S: over edges of r' = 4S+rl, accumulate
//   w[(rl*4+j)][s] += ns'[s]*nd'[d]*u_{4*dst(r')+j}[d]
__global__ void k_wpass(const int* __restrict__ edges, int S) {
    int e = blockIdx.x * blockDim.x + threadIdx.x;
    if (e >= EE) return;
    int rl = blockIdx.y;
    int rp = 4 * S + rl;
    const int* base = edges + rp * 2 * EE;
    int s = base[e], d = base[EE + e];
    float ns = rsqrtf(fmaxf(g_deg[(2 * rp) * NN + s], 1.f));
    float nd = rsqrtf(fmaxf(g_deg[(2 * rp + 1) * NN + d], 1.f));
    float c = ns * nd;
    int dt = c_dst[rp];
#pragma unroll
    for (int j = 0; j < 4; j++) {
        float uv = g_u[(4 * dt + j) * NN + d];
        atomicAdd(&g_w[(rl * 4 + j) * NN + s], c * uv);
    }
}

// 16 simultaneous weighted column sums: y[p][c] += sum_u w[p][u] * x[u][c]
__global__ void k_colsum(const float* __restrict__ x, int F, int ybase) {
    int c = blockIdx.x * 256 + threadIdx.x;
    int u0 = blockIdx.y * CH;
    int u1 = min(u0 + CH, NN);
    __shared__ float sw[16 * 64];
    float acc[16];
#pragma unroll
    for (int p = 0; p < 16; p++) acc[p] = 0.f;
    bool active = (c < F);
    for (int ub = u0; ub < u1; ub += 64) {
        int cnt = min(64, u1 - ub);
        for (int i = threadIdx.x; i < 16 * 64; i += 256) {
            int p = i >> 6, ii = i & 63;
            sw[i] = (ii < cnt) ? g_w[p * NN + ub + ii] : 0.f;
        }
        __syncthreads();
        if (active) {
            if (cnt == 64) {
#pragma unroll 4
                for (int i = 0; i < 64; i++) {
                    float xv = x[(ub + i) * F + c];
#pragma unroll
                    for (int p = 0; p < 16; p++) acc[p] += sw[p * 64 + i] * xv;
                }
            } else {
                for (int i = 0; i < cnt; i++) {
                    float xv = x[(ub + i) * F + c];
#pragma unroll
                    for (int p = 0; p < 16; p++) acc[p] += sw[p * 64 + i] * xv;
                }
            }
        }
        __syncthreads();
    }
    if (active) {
#pragma unroll
        for (int p = 0; p < 16; p++) atomicAdd(&g_y[(ybase + p) * 768 + c], acc[p]);
    }
}

// t_r[j] = sum_{r' in in(s(r))} (y_{(r,r')} @ W1_{r'})[j] + sigma_r * sum b1[r'][j]
__global__ void k_combine(const float* __restrict__ w1s, const float* __restrict__ w1f,
                          const float* __restrict__ w1m, const float* __restrict__ w1n,
                          const float* __restrict__ w1p, const float* __restrict__ b1) {
    int r = blockIdx.x, j = threadIdx.x;
    const float* W1tab[5] = {w1s, w1f, w1m, w1n, w1p};
    int s = r >> 2;
    float sig = g_sigma[r];
    float t = 0.f;
    for (int q = 0; q < 4; q++) {
        int rp = c_inrel[s][q];
        int S2 = rp >> 2;
        int F = c_F[S2];
        const float* W1 = W1tab[S2] + (rp & 3) * F * HH;
        const float* y = &g_y[(rp * 4 + (r & 3)) * 768];
        float a = 0.f;
        for (int cc = 0; cc < F; cc++) a += y[cc] * W1[cc * HH + j];
        t += a + sig * b1[rp * HH + j];
    }
    g_t[r * HH + j] = t;
}

// m[j] = (1/5N) sum_r (t_r @ W2_r)[j] + (1/5) sum_r b2[r][j];  out = m@Wfc + bfc
__global__ void k_final(const float* __restrict__ W2, const float* __restrict__ b2,
                        const float* __restrict__ Wfc, const float* __restrict__ bfc,
                        float* __restrict__ out) {
    __shared__ float sm[HH];
    int j = threadIdx.x;
    float acc = 0.f, bsum = 0.f;
    for (int r = 0; r < NREL; r++) {
        const float* t = &g_t[r * HH];
        const float* W = W2 + r * HH * HH;
        float a = 0.f;
        for (int k = 0; k < HH; k++) a += t[k] * W[k * HH + j];
        acc += a;
        bsum += b2[r * HH + j];
    }
    float m = acc * (1.f / (5.f * (float)NN)) + bsum * 0.2f;
    sm[j] = m;
    out[j] = m;
    __syncthreads();
    if (j < 10) {
        float o = bfc[j];
        for (int k = 0; k < HH; k++) o += sm[k] * Wfc[k * 10 + j];
        out[HH + j] = o;
    }
}

extern "C" void kernel_launch(void* const* d_in, const int* in_sizes, int n_in,
                              void* d_out, int out_size) {
    const float* x[5];
    for (int i = 0; i < 5; i++) x[i] = (const float*)d_in[i];
    const float* w1s = (const float*)d_in[5];
    const float* w1f = (const float*)d_in[6];
    const float* w1m = (const float*)d_in[7];
    const float* w1n = (const float*)d_in[8];
    const float* w1p = (const float*)d_in[9];
    const float* b1  = (const float*)d_in[10];
    const float* W2  = (const float*)d_in[11];
    const float* b2  = (const float*)d_in[12];
    const float* Wfc = (const float*)d_in[13];
    const float* bfc = (const float*)d_in[14];
    const int* edges = (const int*)d_in[15];
    float* out = (float*)d_out;

    const int Fh[5] = {5, 16, 21, 768, 768};

    k_zero_pre<<<2048, 256>>>();
    {
        dim3 g((EE + 255) / 256, NREL);
        k_degree<<<g, 256>>>(edges);
        k_u<<<g, 256>>>(edges);
    }
    k_sigma<<<NREL, 256>>>();

    for (int S = 0; S < 5; S++) {
        k_zero_w<<<1024, 256>>>();
        dim3 gw((EE + 255) / 256, 4);
        k_wpass<<<gw, 256>>>(edges, S);
        int F = Fh[S];
        dim3 gc((F + 255) / 256, (NN + CH - 1) / CH);
        k_colsum<<<gc, 256>>>(x[S], F, 16 * S);
    }

    k_combine<<<NREL, HH>>>(w1s, w1f, w1m, w1n, w1p, b1);
    k_final<<<1, HH>>>(W2, b2, Wfc, bfc, out);
}

// round 2
// speedup vs baseline: 1.0189x; 1.0189x over previous
#include <cuda_runtime.h>

#define NN 50000
#define EE 400000
#define HH 128
#define NREL 20
#define CH 512

// Scratch (device globals; no allocation allowed)
__device__ float g_deg[2 * NREL * NN];   // [r][0]=out-deg(src), [r][1]=in-deg(dst)
__device__ float g_u[NREL * NN];         // u_r = M_r^T 1
__device__ float g_sigma[NREL];          // sum of u_r
__device__ float g_w[16 * NN];           // 16 w vectors per src-ntype group (reused)
__device__ float g_y[80 * 768];          // y[(r'*4 + r%4)][c] = w^T x
__device__ float g_t[NREL * HH];         // t_r = u_r^T h1_{s(r)}

// RELS dst ntype ids (stock=0, financial=1, macro=2, news=3, policy=4)
__constant__ int c_dst[NREL] = {1,2,3,4, 2,0,3,4, 0,1,3,4, 0,1,2,4, 0,2,3,1};
// relations whose dst == given ntype
__constant__ int c_inrel[5][4] = {{5,8,12,16},{0,9,13,19},{1,4,14,17},{2,6,10,18},{3,7,11,15}};
__constant__ int c_F[5] = {5,16,21,768,768};

__global__ void k_zero_pre() {
    const int T1 = 2 * NREL * NN, T2 = NREL * NN, T3 = 80 * 768;
    for (int i = blockIdx.x * blockDim.x + threadIdx.x; i < T1 + T2 + T3;
         i += gridDim.x * blockDim.x) {
        if (i < T1) g_deg[i] = 0.f;
        else if (i < T1 + T2) g_u[i - T1] = 0.f;
        else g_y[i - T1 - T2] = 0.f;
    }
}

__global__ void k_zero_w() {
    for (int i = blockIdx.x * blockDim.x + threadIdx.x; i < 16 * NN;
         i += gridDim.x * blockDim.x) g_w[i] = 0.f;
}

__global__ void k_degree(const int* __restrict__ edges) {
    int e = blockIdx.x * blockDim.x + threadIdx.x;
    if (e >= EE) return;
    int r = blockIdx.y;
    const int* base = edges + r * 2 * EE;
    atomicAdd(&g_deg[(2 * r) * NN + base[e]], 1.f);
    atomicAdd(&g_deg[(2 * r + 1) * NN + base[EE + e]], 1.f);
}

__global__ void k_u(const int* __restrict__ edges) {
    int e = blockIdx.x * blockDim.x + threadIdx.x;
    if (e >= EE) return;
    int r = blockIdx.y;
    const int* base = edges + r * 2 * EE;
    int s = base[e], d = base[EE + e];
    float ns = rsqrtf(fmaxf(g_deg[(2 * r) * NN + s], 1.f));
    float nd = rsqrtf(fmaxf(g_deg[(2 * r + 1) * NN + d], 1.f));
    atomicAdd(&g_u[r * NN + s], ns * nd);
}

__global__ void k_sigma() {
    int r = blockIdx.x;
    float a = 0.f;
    for (int i = threadIdx.x; i < NN; i += blockDim.x) a += g_u[r * NN + i];
    __shared__ float sred[256];
    sred[threadIdx.x] = a;
    __syncthreads();
    for (int st = 128; st > 0; st >>= 1) {
        if (threadIdx.x < st) sred[threadIdx.x] += sred[threadIdx.x + st];
        __syncthreads();
    }
    if (threadIdx.x == 0) g_sigma[r] = sred[0];
}

// For src-ntype S: over edges of r' = 4S+rl, accumulate
//   w[(rl*4+j)][s] += ns'[s]*nd'[d]*u_{4*dst(r')+j}[d]
__global__ void k_wpass(const int* __restrict__ edges, int S) {
    int e = blockIdx.x * blockDim.x + threadIdx.x;
    if (e >= EE) return;
    int rl = blockIdx.y;
    int rp = 4 * S + rl;
    const int* base = edges + rp * 2 * EE;
    int s = base[e], d = base[EE + e];
    float ns = rsqrtf(fmaxf(g_deg[(2 * rp) * NN + s], 1.f));
    float nd = rsqrtf(fmaxf(g_deg[(2 * rp + 1) * NN + d], 1.f));
    float c = ns * nd;
    int dt = c_dst[rp];
#pragma unroll
    for (int j = 0; j < 4; j++) {
        float uv = g_u[(4 * dt + j) * NN + d];
        atomicAdd(&g_w[(rl * 4 + j) * NN + s], c * uv);
    }
}

// 16 simultaneous weighted column sums: y[p][c] += sum_u w[p][u] * x[u][c]
__global__ void k_colsum(const float* __restrict__ x, int F, int ybase) {
    int c = blockIdx.x * 256 + threadIdx.x;
    int u0 = blockIdx.y * CH;
    int u1 = min(u0 + CH, NN);
    __shared__ float sw[16 * 64];
    float acc[16];
#pragma unroll
    for (int p = 0; p < 16; p++) acc[p] = 0.f;
    bool active = (c < F);
    for (int ub = u0; ub < u1; ub += 64) {
        int cnt = min(64, u1 - ub);
        for (int i = threadIdx.x; i < 16 * 64; i += 256) {
            int p = i >> 6, ii = i & 63;
            sw[i] = (ii < cnt) ? g_w[p * NN + ub + ii] : 0.f;
        }
        __syncthreads();
        if (active) {
            if (cnt == 64) {
#pragma unroll 4
                for (int i = 0; i < 64; i++) {
                    float xv = x[(ub + i) * F + c];
#pragma unroll
                    for (int p = 0; p < 16; p++) acc[p] += sw[p * 64 + i] * xv;
                }
            } else {
                for (int i = 0; i < cnt; i++) {
                    float xv = x[(ub + i) * F + c];
#pragma unroll
                    for (int p = 0; p < 16; p++) acc[p] += sw[p * 64 + i] * xv;
                }
            }
        }
        __syncthreads();
    }
    if (active) {
#pragma unroll
        for (int p = 0; p < 16; p++) atomicAdd(&g_y[(ybase + p) * 768 + c], acc[p]);
    }
}

// t_r[j] = sum_{r' in in(s(r))} (y_{(r,r')} @ W1_{r'})[j] + sigma_r * sum b1[r'][j]
__global__ void k_combine(const float* __restrict__ w1s, const float* __restrict__ w1f,
                          const float* __restrict__ w1m, const float* __restrict__ w1n,
                          const float* __restrict__ w1p, const float* __restrict__ b1) {
    int r = blockIdx.x, j = threadIdx.x;
    const float* W1tab[5] = {w1s, w1f, w1m, w1n, w1p};
    int s = r >> 2;
    float sig = g_sigma[r];
    float t = 0.f;
    for (int q = 0; q < 4; q++) {
        int rp = c_inrel[s][q];
        int S2 = rp >> 2;
        int F = c_F[S2];
        const float* W1 = W1tab[S2] + (rp & 3) * F * HH;
        const float* y = &g_y[(rp * 4 + (r & 3)) * 768];
        float a = 0.f;
        for (int cc = 0; cc < F; cc++) a += y[cc] * W1[cc * HH + j];
        t += a + sig * b1[rp * HH + j];
    }
    g_t[r * HH + j] = t;
}

// m[j] = (1/5N) sum_r (t_r @ W2_r)[j] + (1/5) sum_r b2[r][j];  out = m@Wfc + bfc
__global__ void k_final(const float* __restrict__ W2, const float* __restrict__ b2,
                        const float* __restrict__ Wfc, const float* __restrict__ bfc,
                        float* __restrict__ out) {
    __shared__ float sm[HH];
    int j = threadIdx.x;
    float acc = 0.f, bsum = 0.f;
    for (int r = 0; r < NREL; r++) {
        const float* t = &g_t[r * HH];
        const float* W = W2 + r * HH * HH;
        float a = 0.f;
        for (int k = 0; k < HH; k++) a += t[k] * W[k * HH + j];
        acc += a;
        bsum += b2[r * HH + j];
    }
    float m = acc * (1.f / (5.f * (float)NN)) + bsum * 0.2f;
    sm[j] = m;
    out[j] = m;
    __syncthreads();
    if (j < 10) {
        float o = bfc[j];
        for (int k = 0; k < HH; k++) o += sm[k] * Wfc[k * 10 + j];
        out[HH + j] = o;
    }
}

extern "C" void kernel_launch(void* const* d_in, const int* in_sizes, int n_in,
                              void* d_out, int out_size) {
    const float* x[5];
    for (int i = 0; i < 5; i++) x[i] = (const float*)d_in[i];
    const float* w1s = (const float*)d_in[5];
    const float* w1f = (const float*)d_in[6];
    const float* w1m = (const float*)d_in[7];
    const float* w1n = (const float*)d_in[8];
    const float* w1p = (const float*)d_in[9];
    const float* b1  = (const float*)d_in[10];
    const float* W2  = (const float*)d_in[11];
    const float* b2  = (const float*)d_in[12];
    const float* Wfc = (const float*)d_in[13];
    const float* bfc = (const float*)d_in[14];
    const int* edges = (const int*)d_in[15];
    float* out = (float*)d_out;

    const int Fh[5] = {5, 16, 21, 768, 768};

    k_zero_pre<<<2048, 256>>>();
    {
        dim3 g((EE + 255) / 256, NREL);
        k_degree<<<g, 256>>>(edges);
        k_u<<<g, 256>>>(edges);
    }
    k_sigma<<<NREL, 256>>>();

    for (int S = 0; S < 5; S++) {
        k_zero_w<<<1024, 256>>>();
        dim3 gw((EE + 255) / 256, 4);
        k_wpass<<<gw, 256>>>(edges, S);
        int F = Fh[S];
        dim3 gc((F + 255) / 256, (NN + CH - 1) / CH);
        k_colsum<<<gc, 256>>>(x[S], F, 16 * S);
    }

    k_combine<<<NREL, HH>>>(w1s, w1f, w1m, w1n, w1p, b1);
    k_final<<<1, HH>>>(W2, b2, Wfc, bfc, out);
}

// round 3
// speedup vs baseline: 1.5343x; 1.5059x over previous
#include <cuda_runtime.h>

#define NN 50000
#define EE 400000
#define HH 128
#define NREL 20
#define CH 512

// Scratch (device globals; no allocation allowed)
__device__ float  g_deg[2 * NREL * NN];    // [r][0]=out-deg(src), [r][1]=in-deg(dst)
__device__ float4 g_u4[5 * NN];            // u packed: g_u4[g*NN+n].j = u_{4g+j}[n]
__device__ float  g_sigma[NREL];           // sum of u_r
__device__ float4 g_w4[NREL * NN];         // w packed: g_w4[rp*NN+s].j = w_{(rp,j)}[s]
__device__ float  g_y[80 * 768];           // y[(rp*4 + j)][c] = w^T x
__device__ float  g_t[NREL * HH];          // t_r = u_r^T h1_{s(r)}

// RELS dst ntype ids (stock=0, financial=1, macro=2, news=3, policy=4)
__constant__ int c_dst[NREL] = {1,2,3,4, 2,0,3,4, 0,1,3,4, 0,1,2,4, 0,2,3,1};
// relations whose dst == given ntype (ordered so that rel = 4*dst_of(rel) + pos)
__constant__ int c_inrel[5][4] = {{5,8,12,16},{0,9,13,19},{1,4,14,17},{2,6,10,18},{3,7,11,15}};
__constant__ int c_F[5] = {5,16,21,768,768};

__global__ void k_zero() {
    int i = blockIdx.x * blockDim.x + threadIdx.x;
    int stride = gridDim.x * blockDim.x;
    float4 z = make_float4(0.f, 0.f, 0.f, 0.f);
    for (int k = i; k < (2 * NREL * NN) / 4; k += stride) ((float4*)g_deg)[k] = z;
    for (int k = i; k < 5 * NN; k += stride) g_u4[k] = z;
    for (int k = i; k < NREL * NN; k += stride) g_w4[k] = z;
    for (int k = i; k < (80 * 768) / 4; k += stride) ((float4*)g_y)[k] = z;
    for (int k = i; k < (NREL * HH) / 4; k += stride) ((float4*)g_t)[k] = z;
    if (i < NREL) g_sigma[i] = 0.f;
}

__global__ void k_degree(const int* __restrict__ edges) {
    int t = blockIdx.x * blockDim.x + threadIdx.x;
    if (t >= EE / 4) return;
    int r = blockIdx.y;
    const int4* sp = (const int4*)(edges + r * 2 * EE);
    const int4* dp = (const int4*)(edges + r * 2 * EE + EE);
    int4 s = sp[t], d = dp[t];
    float* ds = g_deg + (2 * r) * NN;
    float* dd = ds + NN;
    atomicAdd(&ds[s.x], 1.f); atomicAdd(&ds[s.y], 1.f);
    atomicAdd(&ds[s.z], 1.f); atomicAdd(&ds[s.w], 1.f);
    atomicAdd(&dd[d.x], 1.f); atomicAdd(&dd[d.y], 1.f);
    atomicAdd(&dd[d.z], 1.f); atomicAdd(&dd[d.w], 1.f);
}

__global__ void k_u(const int* __restrict__ edges) {
    int t = blockIdx.x * blockDim.x + threadIdx.x;
    if (t >= EE / 4) return;
    int r = blockIdx.y;
    const int4* sp = (const int4*)(edges + r * 2 * EE);
    const int4* dp = (const int4*)(edges + r * 2 * EE + EE);
    int4 s4 = sp[t], d4 = dp[t];
    const float* ds = g_deg + (2 * r) * NN;
    const float* dd = ds + NN;
    float* ub = (float*)g_u4 + (r >> 2) * NN * 4 + (r & 3);
    int ss[4] = {s4.x, s4.y, s4.z, s4.w};
    int dds[4] = {d4.x, d4.y, d4.z, d4.w};
#pragma unroll
    for (int i = 0; i < 4; i++) {
        float ns = rsqrtf(fmaxf(ds[ss[i]], 1.f));
        float nd = rsqrtf(fmaxf(dd[dds[i]], 1.f));
        atomicAdd(&ub[ss[i] * 4], ns * nd);
    }
}

__global__ void k_sigma() {
    int r = blockIdx.x;
    int g = r >> 2, j = r & 3;
    const float* up = (const float*)g_u4 + g * NN * 4 + j;
    int i0 = blockIdx.y * 6250;
    int i1 = min(i0 + 6250, NN);
    float a = 0.f;
    for (int i = i0 + threadIdx.x; i < i1; i += blockDim.x) a += up[i * 4];
    __shared__ float sred[256];
    sred[threadIdx.x] = a;
    __syncthreads();
    for (int st = 128; st > 0; st >>= 1) {
        if (threadIdx.x < st) sred[threadIdx.x] += sred[threadIdx.x + st];
        __syncthreads();
    }
    if (threadIdx.x == 0) atomicAdd(&g_sigma[r], sred[0]);
}

// For every relation rp: w4[rp][s] += c * u4[dst_type(rp)][d]  (one float4 RED per edge)
__global__ void k_wpass(const int* __restrict__ edges) {
    int t = blockIdx.x * blockDim.x + threadIdx.x;
    if (t >= EE / 4) return;
    int rp = blockIdx.y;
    const int4* sp = (const int4*)(edges + rp * 2 * EE);
    const int4* dp = (const int4*)(edges + rp * 2 * EE + EE);
    int4 s4 = sp[t], d4 = dp[t];
    const float* ds = g_deg + (2 * rp) * NN;
    const float* dd = ds + NN;
    int dt = c_dst[rp];
    const float4* u4 = g_u4 + dt * NN;
    float4* w4 = g_w4 + rp * NN;
    int ss[4] = {s4.x, s4.y, s4.z, s4.w};
    int dds[4] = {d4.x, d4.y, d4.z, d4.w};
#pragma unroll
    for (int i = 0; i < 4; i++) {
        int s = ss[i], d = dds[i];
        float ns = rsqrtf(fmaxf(ds[s], 1.f));
        float nd = rsqrtf(fmaxf(dd[d], 1.f));
        float c = ns * nd;
        float4 uv = u4[d];
        atomicAdd(&w4[s], make_float4(c * uv.x, c * uv.y, c * uv.z, c * uv.w));
    }
}

// 16 simultaneous weighted column sums per src type S:
//   y[16S + p][c] += sum_u w[p][u] * x_S[u][c]
// grid: (3, ceil(NN/CH), 5)
__global__ void k_colsum(const float* __restrict__ xs, const float* __restrict__ xf,
                         const float* __restrict__ xm, const float* __restrict__ xn,
                         const float* __restrict__ xp) {
    int S = blockIdx.z;
    int F = c_F[S];
    if ((int)(blockIdx.x * 256) >= F) return;
    const float* xtab[5] = {xs, xf, xm, xn, xp};
    const float* x = xtab[S];
    int c = blockIdx.x * 256 + threadIdx.x;
    int u0 = blockIdx.y * CH;
    int u1 = min(u0 + CH, NN);
    __shared__ float sw[16 * 64];
    float acc[16];
#pragma unroll
    for (int p = 0; p < 16; p++) acc[p] = 0.f;
    bool active = (c < F);
    const float4* wbase = g_w4 + 4 * S * NN;
    for (int ub = u0; ub < u1; ub += 64) {
        int cnt = min(64, u1 - ub);
        {
            int i = threadIdx.x;       // 256 threads load 4 rels x 64 nodes
            int rl = i >> 6, ii = i & 63;
            float4 v = (ii < cnt) ? wbase[rl * NN + ub + ii]
                                  : make_float4(0.f, 0.f, 0.f, 0.f);
            sw[(rl * 4 + 0) * 64 + ii] = v.x;
            sw[(rl * 4 + 1) * 64 + ii] = v.y;
            sw[(rl * 4 + 2) * 64 + ii] = v.z;
            sw[(rl * 4 + 3) * 64 + ii] = v.w;
        }
        __syncthreads();
        if (active) {
            if (cnt == 64) {
#pragma unroll 4
                for (int i = 0; i < 64; i++) {
                    float xv = x[(ub + i) * F + c];
#pragma unroll
                    for (int p = 0; p < 16; p++) acc[p] += sw[p * 64 + i] * xv;
                }
            } else {
                for (int i = 0; i < cnt; i++) {
                    float xv = x[(ub + i) * F + c];
#pragma unroll
                    for (int p = 0; p < 16; p++) acc[p] += sw[p * 64 + i] * xv;
                }
            }
        }
        __syncthreads();
    }
    if (active) {
#pragma unroll
        for (int p = 0; p < 16; p++) atomicAdd(&g_y[(16 * S + p) * 768 + c], acc[p]);
    }
}

// t_r[j] += (y_{(r,rp)} @ W1_{rp})[j] + sigma_r * b1[rp][j],  rp = c_inrel[src(r)][q]
// grid: (20, 4), block HH
__global__ void k_combine(const float* __restrict__ w1s, const float* __restrict__ w1f,
                          const float* __restrict__ w1m, const float* __restrict__ w1n,
                          const float* __restrict__ w1p, const float* __restrict__ b1) {
    int r = blockIdx.x, q = blockIdx.y, j = threadIdx.x;
    const float* W1tab[5] = {w1s, w1f, w1m, w1n, w1p};
    int s = r >> 2;
    int rp = c_inrel[s][q];
    int S2 = rp >> 2;
    int F = c_F[S2];
    const float* W1 = W1tab[S2] + (rp & 3) * F * HH;
    const float* y = &g_y[(rp * 4 + (r & 3)) * 768];
    float a = 0.f;
    for (int cc = 0; cc < F; cc++) a += y[cc] * W1[cc * HH + j];
    a += g_sigma[r] * b1[rp * HH + j];
    atomicAdd(&g_t[r * HH + j], a);
}

// m[j] = (1/5N) sum_r (t_r @ W2_r)[j] + (1/5) sum_r b2[r][j];  out = m@Wfc + bfc
__global__ void k_final(const float* __restrict__ W2, const float* __restrict__ b2,
                        const float* __restrict__ Wfc, const float* __restrict__ bfc,
                        float* __restrict__ out) {
    __shared__ float sm[HH];
    int j = threadIdx.x;
    float acc = 0.f, bsum = 0.f;
    for (int r = 0; r < NREL; r++) {
        const float* t = &g_t[r * HH];
        const float* W = W2 + r * HH * HH;
        float a = 0.f;
        for (int k = 0; k < HH; k++) a += t[k] * W[k * HH + j];
        acc += a;
        bsum += b2[r * HH + j];
    }
    float m = acc * (1.f / (5.f * (float)NN)) + bsum * 0.2f;
    sm[j] = m;
    out[j] = m;
    __syncthreads();
    if (j < 10) {
        float o = bfc[j];
        for (int k = 0; k < HH; k++) o += sm[k] * Wfc[k * 10 + j];
        out[HH + j] = o;
    }
}

extern "C" void kernel_launch(void* const* d_in, const int* in_sizes, int n_in,
                              void* d_out, int out_size) {
    const float* xs = (const float*)d_in[0];
    const float* xf = (const float*)d_in[1];
    const float* xm = (const float*)d_in[2];
    const float* xn = (const float*)d_in[3];
    const float* xp = (const float*)d_in[4];
    const float* w1s = (const float*)d_in[5];
    const float* w1f = (const float*)d_in[6];
    const float* w1m = (const float*)d_in[7];
    const float* w1n = (const float*)d_in[8];
    const float* w1p = (const float*)d_in[9];
    const float* b1  = (const float*)d_in[10];
    const float* W2  = (const float*)d_in[11];
    const float* b2  = (const float*)d_in[12];
    const float* Wfc = (const float*)d_in[13];
    const float* bfc = (const float*)d_in[14];
    const int* edges = (const int*)d_in[15];
    float* out = (float*)d_out;

    k_zero<<<2048, 256>>>();

    dim3 ge((EE / 4 + 255) / 256, NREL);
    k_degree<<<ge, 256>>>(edges);
    k_u<<<ge, 256>>>(edges);
    k_sigma<<<dim3(NREL, 8), 256>>>();
    k_wpass<<<ge, 256>>>(edges);

    dim3 gc(3, (NN + CH - 1) / CH, 5);
    k_colsum<<<gc, 256>>>(xs, xf, xm, xn, xp);

    k_combine<<<dim3(NREL, 4), HH>>>(w1s, w1f, w1m, w1n, w1p, b1);
    k_final<<<1, HH>>>(W2, b2, Wfc, bfc, out);
}

// round 4
// speedup vs baseline: 1.5396x; 1.0035x over previous
#include <cuda_runtime.h>

#define NN 50000
#define EE 400000
#define HH 128
#define NREL 20
#define CH 512

// Scratch (device globals; no allocation allowed)
__device__ float  g_deg[2 * NREL * NN];    // [r][0]=out-deg(src), [r][1]=in-deg(dst)
__device__ float4 g_u4[5 * NN];            // u packed: g_u4[g*NN+n].j = u_{4g+j}[n]
__device__ float  g_sigma[NREL];           // sum of u_r
__device__ float4 g_w4[NREL * NN];         // w packed: g_w4[rp*NN+s].j = w_{(rp,j)}[s]
__device__ float  g_y[80 * 768];           // y[(rp*4 + j)][c] = w^T x
__device__ float  g_t[NREL * HH];          // t_r = u_r^T h1_{s(r)}

// RELS dst ntype ids (stock=0, financial=1, macro=2, news=3, policy=4)
__constant__ int c_dst[NREL] = {1,2,3,4, 2,0,3,4, 0,1,3,4, 0,1,2,4, 0,2,3,1};
// relations whose dst == given ntype (ordered so that rel = 4*dst_of(rel) + pos)
__constant__ int c_inrel[5][4] = {{5,8,12,16},{0,9,13,19},{1,4,14,17},{2,6,10,18},{3,7,11,15}};
__constant__ int c_F[5] = {5,16,21,768,768};

__global__ void k_zero() {
    int i = blockIdx.x * blockDim.x + threadIdx.x;
    int stride = gridDim.x * blockDim.x;
    float4 z = make_float4(0.f, 0.f, 0.f, 0.f);
    for (int k = i; k < (2 * NREL * NN) / 4; k += stride) ((float4*)g_deg)[k] = z;
    for (int k = i; k < 5 * NN; k += stride) g_u4[k] = z;
    for (int k = i; k < NREL * NN; k += stride) g_w4[k] = z;
    for (int k = i; k < (80 * 768) / 4; k += stride) ((float4*)g_y)[k] = z;
    for (int k = i; k < (NREL * HH) / 4; k += stride) ((float4*)g_t)[k] = z;
    if (i < NREL) g_sigma[i] = 0.f;
}

__global__ void k_degree(const int* __restrict__ edges) {
    int t = blockIdx.x * blockDim.x + threadIdx.x;
    if (t >= EE / 4) return;
    int r = blockIdx.y;
    const int4* sp = (const int4*)(edges + r * 2 * EE);
    const int4* dp = (const int4*)(edges + r * 2 * EE + EE);
    int4 s = sp[t], d = dp[t];
    float* ds = g_deg + (2 * r) * NN;
    float* dd = ds + NN;
    atomicAdd(&ds[s.x], 1.f); atomicAdd(&ds[s.y], 1.f);
    atomicAdd(&ds[s.z], 1.f); atomicAdd(&ds[s.w], 1.f);
    atomicAdd(&dd[d.x], 1.f); atomicAdd(&dd[d.y], 1.f);
    atomicAdd(&dd[d.z], 1.f); atomicAdd(&dd[d.w], 1.f);
}

__global__ void k_u(const int* __restrict__ edges) {
    int t = blockIdx.x * blockDim.x + threadIdx.x;
    if (t >= EE / 4) return;
    int r = blockIdx.y;
    const int4* sp = (const int4*)(edges + r * 2 * EE);
    const int4* dp = (const int4*)(edges + r * 2 * EE + EE);
    int4 s4 = sp[t], d4 = dp[t];
    const float* ds = g_deg + (2 * r) * NN;
    const float* dd = ds + NN;
    float* ub = (float*)g_u4 + (r >> 2) * NN * 4 + (r & 3);
    int ss[4] = {s4.x, s4.y, s4.z, s4.w};
    int dds[4] = {d4.x, d4.y, d4.z, d4.w};
#pragma unroll
    for (int i = 0; i < 4; i++) {
        float ns = rsqrtf(fmaxf(ds[ss[i]], 1.f));
        float nd = rsqrtf(fmaxf(dd[dds[i]], 1.f));
        atomicAdd(&ub[ss[i] * 4], ns * nd);
    }
}

__global__ void k_sigma() {
    int r = blockIdx.x;
    int g = r >> 2, j = r & 3;
    const float* up = (const float*)g_u4 + g * NN * 4 + j;
    int i0 = blockIdx.y * 6250;
    int i1 = min(i0 + 6250, NN);
    float a = 0.f;
    for (int i = i0 + threadIdx.x; i < i1; i += blockDim.x) a += up[i * 4];
    __shared__ float sred[256];
    sred[threadIdx.x] = a;
    __syncthreads();
    for (int st = 128; st > 0; st >>= 1) {
        if (threadIdx.x < st) sred[threadIdx.x] += sred[threadIdx.x + st];
        __syncthreads();
    }
    if (threadIdx.x == 0) atomicAdd(&g_sigma[r], sred[0]);
}

// For every relation rp: w4[rp][s] += c * u4[dst_type(rp)][d]  (one float4 RED per edge)
__global__ void k_wpass(const int* __restrict__ edges) {
    int t = blockIdx.x * blockDim.x + threadIdx.x;
    if (t >= EE / 4) return;
    int rp = blockIdx.y;
    const int4* sp = (const int4*)(edges + rp * 2 * EE);
    const int4* dp = (const int4*)(edges + rp * 2 * EE + EE);
    int4 s4 = sp[t], d4 = dp[t];
    const float* ds = g_deg + (2 * rp) * NN;
    const float* dd = ds + NN;
    int dt = c_dst[rp];
    const float4* u4 = g_u4 + dt * NN;
    float4* w4 = g_w4 + rp * NN;
    int ss[4] = {s4.x, s4.y, s4.z, s4.w};
    int dds[4] = {d4.x, d4.y, d4.z, d4.w};
#pragma unroll
    for (int i = 0; i < 4; i++) {
        int s = ss[i], d = dds[i];
        float ns = rsqrtf(fmaxf(ds[s], 1.f));
        float nd = rsqrtf(fmaxf(dd[d], 1.f));
        float c = ns * nd;
        float4 uv = u4[d];
        atomicAdd(&w4[s], make_float4(c * uv.x, c * uv.y, c * uv.z, c * uv.w));
    }
}

// 16 simultaneous weighted column sums per src type S:
//   y[16S + p][c] += sum_u w[p][u] * x_S[u][c]
// grid: (3, ceil(NN/CH), 5)
__global__ void k_colsum(const float* __restrict__ xs, const float* __restrict__ xf,
                         const float* __restrict__ xm, const float* __restrict__ xn,
                         const float* __restrict__ xp) {
    int S = blockIdx.z;
    int F = c_F[S];
    if ((int)(blockIdx.x * 256) >= F) return;
    const float* xtab[5] = {xs, xf, xm, xn, xp};
    const float* x = xtab[S];
    int c = blockIdx.x * 256 + threadIdx.x;
    int u0 = blockIdx.y * CH;
    int u1 = min(u0 + CH, NN);
    __shared__ float sw[16 * 64];
    float acc[16];
#pragma unroll
    for (int p = 0; p < 16; p++) acc[p] = 0.f;
    bool active = (c < F);
    const float4* wbase = g_w4 + 4 * S * NN;
    for (int ub = u0; ub < u1; ub += 64) {
        int cnt = min(64, u1 - ub);
        {
            int i = threadIdx.x;       // 256 threads load 4 rels x 64 nodes
            int rl = i >> 6, ii = i & 63;
            float4 v = (ii < cnt) ? wbase[rl * NN + ub + ii]
                                  : make_float4(0.f, 0.f, 0.f, 0.f);
            sw[(rl * 4 + 0) * 64 + ii] = v.x;
            sw[(rl * 4 + 1) * 64 + ii] = v.y;
            sw[(rl * 4 + 2) * 64 + ii] = v.z;
            sw[(rl * 4 + 3) * 64 + ii] = v.w;
        }
        __syncthreads();
        if (active) {
            if (cnt == 64) {
#pragma unroll 4
                for (int i = 0; i < 64; i++) {
                    float xv = x[(ub + i) * F + c];
#pragma unroll
                    for (int p = 0; p < 16; p++) acc[p] += sw[p * 64 + i] * xv;
                }
            } else {
                for (int i = 0; i < cnt; i++) {
                    float xv = x[(ub + i) * F + c];
#pragma unroll
                    for (int p = 0; p < 16; p++) acc[p] += sw[p * 64 + i] * xv;
                }
            }
        }
        __syncthreads();
    }
    if (active) {
#pragma unroll
        for (int p = 0; p < 16; p++) atomicAdd(&g_y[(16 * S + p) * 768 + c], acc[p]);
    }
}

// t_r[j] += (y_{(r,rp)} @ W1_{rp})[j] + sigma_r * b1[rp][j],  rp = c_inrel[src(r)][q]
// grid: (20, 4), block HH
__global__ void k_combine(const float* __restrict__ w1s, const float* __restrict__ w1f,
                          const float* __restrict__ w1m, const float* __restrict__ w1n,
                          const float* __restrict__ w1p, const float* __restrict__ b1) {
    int r = blockIdx.x, q = blockIdx.y, j = threadIdx.x;
    const float* W1tab[5] = {w1s, w1f, w1m, w1n, w1p};
    int s = r >> 2;
    int rp = c_inrel[s][q];
    int S2 = rp >> 2;
    int F = c_F[S2];
    const float* W1 = W1tab[S2] + (rp & 3) * F * HH;
    const float* y = &g_y[(rp * 4 + (r & 3)) * 768];
    float a = 0.f;
    for (int cc = 0; cc < F; cc++) a += y[cc] * W1[cc * HH + j];
    a += g_sigma[r] * b1[rp * HH + j];
    atomicAdd(&g_t[r * HH + j], a);
}

// m[j] = (1/5N) sum_r (t_r @ W2_r)[j] + (1/5) sum_r b2[r][j];  out = m@Wfc + bfc
__global__ void k_final(const float* __restrict__ W2, const float* __restrict__ b2,
                        const float* __restrict__ Wfc, const float* __restrict__ bfc,
                        float* __restrict__ out) {
    __shared__ float sm[HH];
    int j = threadIdx.x;
    float acc = 0.f, bsum = 0.f;
    for (int r = 0; r < NREL; r++) {
        const float* t = &g_t[r * HH];
        const float* W = W2 + r * HH * HH;
        float a = 0.f;
        for (int k = 0; k < HH; k++) a += t[k] * W[k * HH + j];
        acc += a;
        bsum += b2[r * HH + j];
    }
    float m = acc * (1.f / (5.f * (float)NN)) + bsum * 0.2f;
    sm[j] = m;
    out[j] = m;
    __syncthreads();
    if (j < 10) {
        float o = bfc[j];
        for (int k = 0; k < HH; k++) o += sm[k] * Wfc[k * 10 + j];
        out[HH + j] = o;
    }
}

extern "C" void kernel_launch(void* const* d_in, const int* in_sizes, int n_in,
                              void* d_out, int out_size) {
    const float* xs = (const float*)d_in[0];
    const float* xf = (const float*)d_in[1];
    const float* xm = (const float*)d_in[2];
    const float* xn = (const float*)d_in[3];
    const float* xp = (const float*)d_in[4];
    const float* w1s = (const float*)d_in[5];
    const float* w1f = (const float*)d_in[6];
    const float* w1m = (const float*)d_in[7];
    const float* w1n = (const float*)d_in[8];
    const float* w1p = (const float*)d_in[9];
    const float* b1  = (const float*)d_in[10];
    const float* W2  = (const float*)d_in[11];
    const float* b2  = (const float*)d_in[12];
    const float* Wfc = (const float*)d_in[13];
    const float* bfc = (const float*)d_in[14];
    const int* edges = (const int*)d_in[15];
    float* out = (float*)d_out;

    k_zero<<<2048, 256>>>();

    dim3 ge((EE / 4 + 255) / 256, NREL);
    k_degree<<<ge, 256>>>(edges);
    k_u<<<ge, 256>>>(edges);
    k_sigma<<<dim3(NREL, 8), 256>>>();
    k_wpass<<<ge, 256>>>(edges);

    dim3 gc(3, (NN + CH - 1) / CH, 5);
    k_colsum<<<gc, 256>>>(xs, xf, xm, xn, xp);

    k_combine<<<dim3(NREL, 4), HH>>>(w1s, w1f, w1m, w1n, w1p, b1);
    k_final<<<1, HH>>>(W2, b2, Wfc, bfc, out);
}

// round 5
// speedup vs baseline: 1.5702x; 1.0199x over previous
#include <cuda_runtime.h>

#define NN 50000
#define EE 400000
#define HH 128
#define NREL 20
#define CH 512

// Scratch (device globals; no allocation allowed)
__device__ float  g_deg[2 * NREL * NN];    // degrees -> then rsqrt-normalized in place
__device__ float4 g_u4[5 * NN];            // u packed: g_u4[g*NN+n].j = u_{4g+j}[n]
__device__ float  g_sigma[NREL];           // sum of u_r = sum of edge coefficients
__device__ float  g_c[NREL * EE];          // per-edge coefficient ns[s]*nd[d]
__device__ float4 g_w4[NREL * NN];         // w packed: g_w4[rp*NN+s].j = w_{(rp,j)}[s]
__device__ float  g_y[80 * 768];           // y[(rp*4 + j)][c] = w^T x
__device__ float  g_t[NREL * HH];          // t_r = u_r^T h1_{s(r)}

// RELS dst ntype ids (stock=0, financial=1, macro=2, news=3, policy=4)
__constant__ int c_dst[NREL] = {1,2,3,4, 2,0,3,4, 0,1,3,4, 0,1,2,4, 0,2,3,1};
// relations whose dst == given ntype
__constant__ int c_inrel[5][4] = {{5,8,12,16},{0,9,13,19},{1,4,14,17},{2,6,10,18},{3,7,11,15}};
__constant__ int c_F[5] = {5,16,21,768,768};

__global__ void k_zero() {
    int i = blockIdx.x * blockDim.x + threadIdx.x;
    int stride = gridDim.x * blockDim.x;
    float4 z = make_float4(0.f, 0.f, 0.f, 0.f);
    for (int k = i; k < (2 * NREL * NN) / 4; k += stride) ((float4*)g_deg)[k] = z;
    for (int k = i; k < 5 * NN; k += stride) g_u4[k] = z;
    for (int k = i; k < NREL * NN; k += stride) g_w4[k] = z;
    for (int k = i; k < (80 * 768) / 4; k += stride) ((float4*)g_y)[k] = z;
    for (int k = i; k < (NREL * HH) / 4; k += stride) ((float4*)g_t)[k] = z;
    if (i < NREL) g_sigma[i] = 0.f;
}

__global__ void k_degree(const int* __restrict__ edges) {
    int t = blockIdx.x * blockDim.x + threadIdx.x;
    if (t >= EE / 4) return;
    int r = blockIdx.y;
    const int4* sp = (const int4*)(edges + r * 2 * EE);
    const int4* dp = (const int4*)(edges + r * 2 * EE + EE);
    int4 s = sp[t], d = dp[t];
    float* ds = g_deg + (2 * r) * NN;
    float* dd = ds + NN;
    atomicAdd(&ds[s.x], 1.f); atomicAdd(&ds[s.y], 1.f);
    atomicAdd(&ds[s.z], 1.f); atomicAdd(&ds[s.w], 1.f);
    atomicAdd(&dd[d.x], 1.f); atomicAdd(&dd[d.y], 1.f);
    atomicAdd(&dd[d.z], 1.f); atomicAdd(&dd[d.w], 1.f);
}

// in-place: deg -> rsqrt(max(deg,1))
__global__ void k_norm() {
    int i = blockIdx.x * blockDim.x + threadIdx.x;
    int stride = gridDim.x * blockDim.x;
    float4* p = (float4*)g_deg;
    for (int k = i; k < (2 * NREL * NN) / 4; k += stride) {
        float4 v = p[k];
        v.x = rsqrtf(fmaxf(v.x, 1.f));
        v.y = rsqrtf(fmaxf(v.y, 1.f));
        v.z = rsqrtf(fmaxf(v.z, 1.f));
        v.w = rsqrtf(fmaxf(v.w, 1.f));
        p[k] = v;
    }
}

// per-edge coeff c = ns[s]*nd[d]; u[s] += c; sigma_r += c (block-reduced)
__global__ void k_u(const int* __restrict__ edges) {
    int t = blockIdx.x * blockDim.x + threadIdx.x;
    int r = blockIdx.y;
    bool valid = (t < EE / 4);
    float csum = 0.f;
    if (valid) {
        const int4* sp = (const int4*)(edges + r * 2 * EE);
        const int4* dp = (const int4*)(edges + r * 2 * EE + EE);
        int4 s4 = sp[t], d4 = dp[t];
        const float* ns_ = g_deg + (2 * r) * NN;
        const float* nd_ = ns_ + NN;
        float4 c;
        c.x = ns_[s4.x] * nd_[d4.x];
        c.y = ns_[s4.y] * nd_[d4.y];
        c.z = ns_[s4.z] * nd_[d4.z];
        c.w = ns_[s4.w] * nd_[d4.w];
        ((float4*)(g_c + r * EE))[t] = c;
        float* ub = (float*)g_u4 + (r >> 2) * NN * 4 + (r & 3);
        atomicAdd(&ub[s4.x * 4], c.x);
        atomicAdd(&ub[s4.y * 4], c.y);
        atomicAdd(&ub[s4.z * 4], c.z);
        atomicAdd(&ub[s4.w * 4], c.w);
        csum = c.x + c.y + c.z + c.w;
    }
    __shared__ float sred[256];
    sred[threadIdx.x] = csum;
    __syncthreads();
    for (int st = 128; st > 0; st >>= 1) {
        if (threadIdx.x < st) sred[threadIdx.x] += sred[threadIdx.x + st];
        __syncthreads();
    }
    if (threadIdx.x == 0) atomicAdd(&g_sigma[r], sred[0]);
}

// w4[rp][s] += c_e * u4[dst_type(rp)][d]  (one float4 RED per edge)
__global__ void k_wpass(const int* __restrict__ edges) {
    int t = blockIdx.x * blockDim.x + threadIdx.x;
    if (t >= EE / 4) return;
    int rp = blockIdx.y;
    const int4* sp = (const int4*)(edges + rp * 2 * EE);
    const int4* dp = (const int4*)(edges + rp * 2 * EE + EE);
    int4 s4 = sp[t], d4 = dp[t];
    float4 c = ((const float4*)(g_c + rp * EE))[t];
    int dt = c_dst[rp];
    const float4* u4 = g_u4 + dt * NN;
    float4* w4 = g_w4 + rp * NN;
    int ss[4] = {s4.x, s4.y, s4.z, s4.w};
    int dds[4] = {d4.x, d4.y, d4.z, d4.w};
    float cc[4] = {c.x, c.y, c.z, c.w};
#pragma unroll
    for (int i = 0; i < 4; i++) {
        float4 uv = u4[dds[i]];
        float k = cc[i];
        atomicAdd(&w4[ss[i]], make_float4(k * uv.x, k * uv.y, k * uv.z, k * uv.w));
    }
}

// 16 simultaneous weighted column sums per src type S, 4 columns/thread:
//   y[16S + p][c] += sum_u w[p][u] * x_S[u][c]
// grid: (1, ceil(NN/CH), 5), block 256 (covers up to 1024 columns)
__global__ void k_colsum(const float* __restrict__ xs, const float* __restrict__ xf,
                         const float* __restrict__ xm, const float* __restrict__ xn,
                         const float* __restrict__ xp) {
    int S = blockIdx.z;
    int F = c_F[S];
    const float* xtab[5] = {xs, xf, xm, xn, xp};
    const float* x = xtab[S];
    int c0 = threadIdx.x * 4;
    int u0 = blockIdx.y * CH;
    int u1 = min(u0 + CH, NN);
    bool vec = ((F & 3) == 0);
    bool active = vec ? (c0 < F) : (c0 < F + 3 && c0 < F);  // any of the 4 cols valid
    if (!vec) active = (c0 < F);
    __shared__ float sw[16 * 64];
    float acc[64];
#pragma unroll
    for (int k = 0; k < 64; k++) acc[k] = 0.f;
    const float4* wbase = g_w4 + 4 * S * NN;
    for (int ub = u0; ub < u1; ub += 64) {
        int cnt = min(64, u1 - ub);
        {
            int i = threadIdx.x;   // 256 threads: 4 rels x 64 nodes
            int rl = i >> 6, ii = i & 63;
            float4 v = (ii < cnt) ? wbase[rl * NN + ub + ii]
                                  : make_float4(0.f, 0.f, 0.f, 0.f);
            sw[(rl * 4 + 0) * 64 + ii] = v.x;
            sw[(rl * 4 + 1) * 64 + ii] = v.y;
            sw[(rl * 4 + 2) * 64 + ii] = v.z;
            sw[(rl * 4 + 3) * 64 + ii] = v.w;
        }
        __syncthreads();
        if (active) {
            if (vec) {
                const float* xr = x + (size_t)ub * F + c0;
#pragma unroll 4
                for (int i = 0; i < 64; i++) {
                    if (i >= cnt) break;
                    float4 xv = *(const float4*)(xr + (size_t)i * F);
#pragma unroll
                    for (int p = 0; p < 16; p++) {
                        float s = sw[p * 64 + i];
                        acc[p * 4 + 0] += s * xv.x;
                        acc[p * 4 + 1] += s * xv.y;
                        acc[p * 4 + 2] += s * xv.z;
                        acc[p * 4 + 3] += s * xv.w;
                    }
                }
            } else {
                for (int i = 0; i < cnt; i++) {
                    const float* xr = x + (size_t)(ub + i) * F;
                    float xv[4];
#pragma unroll
                    for (int v = 0; v < 4; v++)
                        xv[v] = (c0 + v < F) ? xr[c0 + v] : 0.f;
#pragma unroll
                    for (int p = 0; p < 16; p++) {
                        float s = sw[p * 64 + i];
                        acc[p * 4 + 0] += s * xv[0];
                        acc[p * 4 + 1] += s * xv[1];
                        acc[p * 4 + 2] += s * xv[2];
                        acc[p * 4 + 3] += s * xv[3];
                    }
                }
            }
        }
        __syncthreads();
    }
    if (active) {
#pragma unroll
        for (int p = 0; p < 16; p++) {
#pragma unroll
            for (int v = 0; v < 4; v++) {
                if (c0 + v < F)
                    atomicAdd(&g_y[(16 * S + p) * 768 + c0 + v], acc[p * 4 + v]);
            }
        }
    }
}

// t_r[j] += (y_{(r,rp)} @ W1_{rp})[j] + sigma_r * b1[rp][j],  rp = c_inrel[src(r)][q]
__global__ void k_combine(const float* __restrict__ w1s, const float* __restrict__ w1f,
                          const float* __restrict__ w1m, const float* __restrict__ w1n,
                          const float* __restrict__ w1p, const float* __restrict__ b1) {
    int r = blockIdx.x, q = blockIdx.y, j = threadIdx.x;
    const float* W1tab[5] = {w1s, w1f, w1m, w1n, w1p};
    int s = r >> 2;
    int rp = c_inrel[s][q];
    int S2 = rp >> 2;
    int F = c_F[S2];
    const float* W1 = W1tab[S2] + (rp & 3) * F * HH;
    const float* y = &g_y[(rp * 4 + (r & 3)) * 768];
    float a = 0.f;
    for (int cc = 0; cc < F; cc++) a += y[cc] * W1[cc * HH + j];
    a += g_sigma[r] * b1[rp * HH + j];
    atomicAdd(&g_t[r * HH + j], a);
}

// m[j] = (1/5N) sum_r (t_r @ W2_r)[j] + (1/5) sum_r b2[r][j];  out = m@Wfc + bfc
__global__ void k_final(const float* __restrict__ W2, const float* __restrict__ b2,
                        const float* __restrict__ Wfc, const float* __restrict__ bfc,
                        float* __restrict__ out) {
    __shared__ float sm[HH];
    int j = threadIdx.x;
    float acc = 0.f, bsum = 0.f;
    for (int r = 0; r < NREL; r++) {
        const float* t = &g_t[r * HH];
        const float* W = W2 + r * HH * HH;
        float a = 0.f;
        for (int k = 0; k < HH; k++) a += t[k] * W[k * HH + j];
        acc += a;
        bsum += b2[r * HH + j];
    }
    float m = acc * (1.f / (5.f * (float)NN)) + bsum * 0.2f;
    sm[j] = m;
    out[j] = m;
    __syncthreads();
    if (j < 10) {
        float o = bfc[j];
        for (int k = 0; k < HH; k++) o += sm[k] * Wfc[k * 10 + j];
        out[HH + j] = o;
    }
}

extern "C" void kernel_launch(void* const* d_in, const int* in_sizes, int n_in,
                              void* d_out, int out_size) {
    const float* xs = (const float*)d_in[0];
    const float* xf = (const float*)d_in[1];
    const float* xm = (const float*)d_in[2];
    const float* xn = (const float*)d_in[3];
    const float* xp = (const float*)d_in[4];
    const float* w1s = (const float*)d_in[5];
    const float* w1f = (const float*)d_in[6];
    const float* w1m = (const float*)d_in[7];
    const float* w1n = (const float*)d_in[8];
    const float* w1p = (const float*)d_in[9];
    const float* b1  = (const float*)d_in[10];
    const float* W2  = (const float*)d_in[11];
    const float* b2  = (const float*)d_in[12];
    const float* Wfc = (const float*)d_in[13];
    const float* bfc = (const float*)d_in[14];
    const int* edges = (const int*)d_in[15];
    float* out = (float*)d_out;

    k_zero<<<2048, 256>>>();

    dim3 ge((EE / 4 + 255) / 256, NREL);
    k_degree<<<ge, 256>>>(edges);
    k_norm<<<2048, 256>>>();
    k_u<<<ge, 256>>>(edges);
    k_wpass<<<ge, 256>>>(edges);

    dim3 gc(1, (NN + CH - 1) / CH, 5);
    k_colsum<<<gc, 256>>>(xs, xf, xm, xn, xp);

    k_combine<<<dim3(NREL, 4), HH>>>(w1s, w1f, w1m, w1n, w1p, b1);
    k_final<<<1, HH>>>(W2, b2, Wfc, bfc, out);
}